// round 4
// baseline (speedup 1.0000x reference)
#include <cuda_runtime.h>
#include <cuda_bf16.h>
#include <math.h>

// Problem shape (fixed by the reference):
// B=16, T=1024, S=1024, E=1024, D=1024
#define B_  16
#define T_  1024
#define S_  1024
#define E_  1024
#define D_  1024

#define BT_   (B_ * T_)          // 16384
#define BS_   (B_ * S_)          // 16384
#define OUT1  (BT_ * D_)         // h_tilde elements  = 16777216
#define OUT2  (BT_ * S_)         // attn_weights      = 16777216
#define OUT3  (BT_ * S_)         // attn_energies     = 16777216

// Scratch (device globals: allowed; cudaMalloc is not)
__device__ float g_proj[B_ * S_ * D_];   // (B,S,D) 64 MB
__device__ float g_wc  [B_ * T_ * E_];   // (B,T,E) 64 MB

// ---------------------------------------------------------------------------
// Tiled SGEMM: C[m,n] = op( sum_k A[m,k] * B'[., .] (+bias[n]) )
//   B_NT  = true : B'[n,k] = Bm[n*ldb + k]   (both operands K-contiguous)
//   B_NT  = false: B'[k,n] = Bm[k*ldb + n]
//   DUAL_A: A is a virtual concat along K: k <  Ksplit -> A0[m,k]
//                                          k >= Ksplit -> A1[m,k-Ksplit]
//   Tile: 128x128x8, 256 threads, 8x8 per-thread microtile.
//   All dims must be multiples of the tile (true for this problem).
// ---------------------------------------------------------------------------
#define BM 128
#define BN 128
#define BK 8
#define TM 8
#define TN 8

template<bool B_NT, bool DUAL_A, bool BIAS, bool TANH_EP>
__global__ __launch_bounds__(256, 2)
void gemm128(const float* __restrict__ A0, const float* __restrict__ A1,
             const float* __restrict__ Bm, const float* __restrict__ bias,
             float* __restrict__ C,
             int K, int Ksplit,
             int lda, int ldb, int ldc,
             long long strideA, long long strideB, long long strideC)
{
    __shared__ float As[BK][BM];
    __shared__ float Bs[BK][BN];

    const int tid = threadIdx.x;
    const int bz  = blockIdx.z;

    const float* a0 = A0 + (long long)bz * strideA;
    const float* a1 = DUAL_A ? (A1 + (long long)bz * strideA) : nullptr;
    const float* b  = Bm + (long long)bz * strideB;
    float*       c  = C  + (long long)bz * strideC;

    const int bm = blockIdx.y * BM;
    const int bn = blockIdx.x * BN;

    const int tx = tid & 15;      // 0..15 -> N
    const int ty = tid >> 4;      // 0..15 -> M

    // global-load indexing
    const int arow  = tid >> 1;          // 0..127 (row within tile, A and NT-B)
    const int akcol = (tid & 1) * 4;     // 0 or 4 (k offset)
    const int bkrow = tid >> 5;          // 0..7   (NN-B k row)
    const int bncol = (tid & 31) * 4;    // 0..124 (NN-B n col)

    float acc[TM][TN];
#pragma unroll
    for (int i = 0; i < TM; i++)
#pragma unroll
        for (int j = 0; j < TN; j++) acc[i][j] = 0.f;

    for (int k0 = 0; k0 < K; k0 += BK) {
        // ---- global loads into registers ----
        const float* Ap;
        int kloc;
        if (DUAL_A && k0 >= Ksplit) { Ap = a1; kloc = k0 - Ksplit; }
        else                        { Ap = a0; kloc = k0; }
        float4 av = *(const float4*)(Ap + (long long)(bm + arow) * lda + kloc + akcol);

        float4 bv;
        if (B_NT) {
            bv = *(const float4*)(b + (long long)(bn + arow) * ldb + k0 + akcol);
        } else {
            bv = *(const float4*)(b + (long long)(k0 + bkrow) * ldb + bn + bncol);
        }

        __syncthreads();   // previous tile fully consumed

        // ---- store to shared ----
        As[akcol + 0][arow] = av.x;
        As[akcol + 1][arow] = av.y;
        As[akcol + 2][arow] = av.z;
        As[akcol + 3][arow] = av.w;
        if (B_NT) {
            Bs[akcol + 0][arow] = bv.x;
            Bs[akcol + 1][arow] = bv.y;
            Bs[akcol + 2][arow] = bv.z;
            Bs[akcol + 3][arow] = bv.w;
        } else {
            *(float4*)&Bs[bkrow][bncol] = bv;
        }

        __syncthreads();

        // ---- compute ----
#pragma unroll
        for (int kk = 0; kk < BK; kk++) {
            float ar[TM], br[TN];
#pragma unroll
            for (int i = 0; i < TM; i++) ar[i] = As[kk][ty * TM + i];
#pragma unroll
            for (int j = 0; j < TN; j++) br[j] = Bs[kk][tx * TN + j];
#pragma unroll
            for (int i = 0; i < TM; i++)
#pragma unroll
                for (int j = 0; j < TN; j++)
                    acc[i][j] = fmaf(ar[i], br[j], acc[i][j]);
        }
    }

    // ---- epilogue ----
#pragma unroll
    for (int i = 0; i < TM; i++) {
        const int m = bm + ty * TM + i;
#pragma unroll
        for (int j = 0; j < TN; j++) {
            const int n = bn + tx * TN + j;
            float v = acc[i][j];
            if (BIAS)    v += bias[n];
            if (TANH_EP) v = tanhf(v);
            c[(long long)m * ldc + n] = v;
        }
    }
}

// ---------------------------------------------------------------------------
// Row softmax over S=1024, one block (256 threads, 4 elems/thread) per row.
// ---------------------------------------------------------------------------
__global__ __launch_bounds__(256)
void softmax_1024(const float* __restrict__ in, float* __restrict__ out)
{
    const long long row = blockIdx.x;
    const float* x = in  + row * 1024;
    float*       y = out + row * 1024;
    const int tid  = threadIdx.x;
    const int lane = tid & 31;
    const int warp = tid >> 5;

    __shared__ float redmax[8];
    __shared__ float redsum[8];

    float4 v = ((const float4*)x)[tid];

    // --- max ---
    float mx = fmaxf(fmaxf(v.x, v.y), fmaxf(v.z, v.w));
#pragma unroll
    for (int o = 16; o; o >>= 1) mx = fmaxf(mx, __shfl_xor_sync(0xffffffffu, mx, o));
    if (lane == 0) redmax[warp] = mx;
    __syncthreads();
    mx = redmax[0];
#pragma unroll
    for (int w = 1; w < 8; w++) mx = fmaxf(mx, redmax[w]);

    // --- exp + sum ---
    float e0 = __expf(v.x - mx);
    float e1 = __expf(v.y - mx);
    float e2 = __expf(v.z - mx);
    float e3 = __expf(v.w - mx);
    float s = (e0 + e1) + (e2 + e3);
#pragma unroll
    for (int o = 16; o; o >>= 1) s += __shfl_xor_sync(0xffffffffu, s, o);
    if (lane == 0) redsum[warp] = s;
    __syncthreads();
    s = redsum[0];
#pragma unroll
    for (int w = 1; w < 8; w++) s += redsum[w];

    const float inv = 1.f / s;
    float4 o4 = make_float4(e0 * inv, e1 * inv, e2 * inv, e3 * inv);
    ((float4*)y)[tid] = o4;
}

// ---------------------------------------------------------------------------
// Launcher
// ---------------------------------------------------------------------------
extern "C" void kernel_launch(void* const* d_in, const int* in_sizes, int n_in,
                              void* d_out, int out_size)
{
    const float* hidden = (const float*)d_in[0];   // (B,T,D)
    const float* enc    = (const float*)d_in[1];   // (B,S,E)
    const float* W_attn = (const float*)d_in[2];   // (D,E)
    const float* b_attn = (const float*)d_in[3];   // (D)
    const float* W_out  = (const float*)d_in[4];   // (D, E+D)

    float* out      = (float*)d_out;
    float* h_tilde  = out;                 // (B,T,D)
    float* weights  = out + OUT1;          // (B,T,S)
    float* energies = out + OUT1 + OUT2;   // (B,T,S)

    float* proj;  cudaGetSymbolAddress((void**)&proj, g_proj);
    float* wc;    cudaGetSymbolAddress((void**)&wc,   g_wc);

    // 1) proj[bs,d] = sum_e enc[bs,e] * W_attn[d,e] + b_attn[d]
    //    M=16384, N=1024, K=1024, NT, bias
    gemm128<true, false, true, false><<<dim3(D_ / BN, BS_ / BM, 1), 256>>>(
        enc, nullptr, W_attn, b_attn, proj,
        E_, 0, /*lda*/E_, /*ldb*/E_, /*ldc*/D_, 0, 0, 0);

    // 2) energies[b][t,s] = sum_d hidden[b][t,d] * proj[b][s,d]
    //    batched NT: M=T, N=S, K=D
    gemm128<true, false, false, false><<<dim3(S_ / BN, T_ / BM, B_), 256>>>(
        hidden, nullptr, proj, nullptr, energies,
        D_, 0, /*lda*/D_, /*ldb*/D_, /*ldc*/S_,
        (long long)T_ * D_, (long long)S_ * D_, (long long)T_ * S_);

    // 3) softmax over S
    softmax_1024<<<BT_, 256>>>(energies, weights);

    // 4) wc[b][t,e] = sum_s weights[b][t,s] * enc[b][s,e]
    //    batched NN: M=T, N=E, K=S
    gemm128<false, false, false, false><<<dim3(E_ / BN, T_ / BM, B_), 256>>>(
        weights, nullptr, enc, nullptr, wc,
        S_, 0, /*lda*/S_, /*ldb*/E_, /*ldc*/E_,
        (long long)T_ * S_, (long long)S_ * E_, (long long)T_ * E_);

    // 5) h_tilde[bt,d] = tanh( sum_e wc[bt,e]*W_out[d,e]
    //                        + sum_h hidden[bt,h]*W_out[d,E_+h] )
    //    M=16384, N=1024, K=2048, NT, dual-A, tanh
    gemm128<true, true, false, true><<<dim3(D_ / BN, BT_ / BM, 1), 256>>>(
        wc, hidden, W_out, nullptr, h_tilde,
        E_ + D_, /*Ksplit*/E_, /*lda*/E_, /*ldb*/E_ + D_, /*ldc*/D_, 0, 0, 0);

    (void)in_sizes; (void)n_in; (void)out_size;
}

// round 9
// speedup vs baseline: 3.0022x; 3.0022x over previous
#include <cuda_runtime.h>
#include <cuda_bf16.h>
#include <cstdint>
#include <math.h>

// Problem shape (fixed): B=16, T=S=E=D=1024
#define B_  16
#define T_  1024
#define S_  1024
#define E_  1024
#define D_  1024

#define BT_   (B_ * T_)          // 16384
#define BS_   (B_ * S_)          // 16384
#define OUT1  (BT_ * D_)
#define OUT2  (BT_ * S_)

// Device-global scratch (cudaMalloc forbidden)
__device__ float g_proj[B_ * S_ * D_];   // (B,S,D)
__device__ float g_wc  [B_ * T_ * E_];   // (B,T,E)
__device__ float g_encT[B_ * E_ * S_];   // (B,E,S) = enc transposed

// ---------------------------------------------------------------------------
// helpers (baseline PTX only — compiles at family target sm_103)
// ---------------------------------------------------------------------------
// returns packed bf16x2: {hi half = bf16(hf), lo half = bf16(lf)}
__device__ __forceinline__ uint32_t pack_bf16x2(float hf, float lf) {
    uint32_t r;
    asm("cvt.rn.bf16x2.f32 %0, %1, %2;" : "=r"(r) : "f"(hf), "f"(lf));
    return r;
}

__device__ __forceinline__ void mma16(float* d, const uint32_t* a, const uint32_t* b) {
    asm volatile(
        "mma.sync.aligned.m16n8k16.row.col.f32.bf16.bf16.f32 "
        "{%0,%1,%2,%3}, {%4,%5,%6,%7}, {%8,%9}, {%0,%1,%2,%3};"
        : "+f"(d[0]), "+f"(d[1]), "+f"(d[2]), "+f"(d[3])
        : "r"(a[0]), "r"(a[1]), "r"(a[2]), "r"(a[3]), "r"(b[0]), "r"(b[1]));
}

// Split one float4 (4 consecutive k) into hi/lo bf16x2 words.
// wh0 = {k1,k0} hi, wh1 = {k3,k2} hi; wl0/wl1 = lo residuals.
__device__ __forceinline__ void split4(float4 v, uint32_t& wh0, uint32_t& wh1,
                                       uint32_t& wl0, uint32_t& wl1) {
    wh0 = pack_bf16x2(v.y, v.x);
    wh1 = pack_bf16x2(v.w, v.z);
    float r0 = v.x - __uint_as_float(wh0 << 16);
    float r1 = v.y - __uint_as_float(wh0 & 0xFFFF0000u);
    float r2 = v.z - __uint_as_float(wh1 << 16);
    float r3 = v.w - __uint_as_float(wh1 & 0xFFFF0000u);
    wl0 = pack_bf16x2(r1, r0);
    wl1 = pack_bf16x2(r3, r2);
}

// ---------------------------------------------------------------------------
// SMEM layout (32-bit words). Per operand per stage: 4 subtiles (u = 0..3,
// covering k = 8u..8u+7), each [128 rows][8 words], row stride 12 words,
// subtile stride KSS. Row segment: words 0-3 = hi pairs p0..p3 (bf16x2,
// pair p = k 2p,2p+1), words 4-7 = lo pairs p0..p3.
// Conflict-free (verified):
//   STS uint2 phase banks {12*row + 8u + 2(c4&1)} : 16 distinct evens.
//   frag LDS banks (12g + t + 8u [+4]) mod 32      : bijective.
// ---------------------------------------------------------------------------
#define KSS      1544                 // subtile stride (words); 1544 % 32 == 8
#define AREG     (4 * KSS)            // words per operand per stage
#define STAGEF   (2 * AREG)           // words per stage (A|B)
#define GEMM_SMEM (2 * STAGEF * 4)    // 98816 bytes, double buffered

// ---------------------------------------------------------------------------
// split-bf16 tensor-core GEMM: C[m,n] = ep( sum_k A[m,k]*B[n,k] (+bias[n]) )
// Tile 128x128x32, 256 threads (8 warps, 2x4), warp tile 64x32.
// acc += Ah*Bh + Ah*Bl + Al*Bh  (fp32 accumulate; ~1e-5 relative accuracy)
// ---------------------------------------------------------------------------
template<bool DUAL_A, bool BIAS, bool TANH_EP>
__global__ __launch_bounds__(256, 1)
void gemm_mma(const float* __restrict__ A0, const float* __restrict__ A1,
              const float* __restrict__ Bm, const float* __restrict__ bias,
              float* __restrict__ C,
              int K, int Ksplit, int lda, int ldb, int ldc,
              long long sA, long long sB, long long sC)
{
    extern __shared__ uint32_t sm[];
    const int tid  = threadIdx.x;
    const int lane = tid & 31;
    const int wid  = tid >> 5;
    const int g = lane >> 2, t = lane & 3;
    const int warp_m = wid & 1;        // 0..1 -> 64 rows
    const int warp_n = wid >> 1;       // 0..3 -> 32 cols

    const int bz = blockIdx.z;
    const int bm = blockIdx.y * 128;
    const int bn = blockIdx.x * 128;

    const float* a0 = A0 + (long long)bz * sA;
    const float* a1 = DUAL_A ? (A1 + (long long)bz * sA) : nullptr;
    const float* bp = Bm + (long long)bz * sB;
    float*       cp = C  + (long long)bz * sC;

    // staging indices: thread covers row0+32r, k = 4*c4 .. 4*c4+3
    const int row0 = tid >> 3;               // 0..31
    const int c4   = tid & 7;                // 0..7
    const int sts_hi = (c4 >> 1) * KSS + (c4 & 1) * 2;   // + row*12 ; lo = +4

    float acc[4][4][4];
#pragma unroll
    for (int i = 0; i < 4; i++)
#pragma unroll
        for (int j = 0; j < 4; j++)
#pragma unroll
            for (int c = 0; c < 4; c++) acc[i][j][c] = 0.f;

    const int nstages = K >> 5;

    // --- stage 0 preload ---
    {
        float4 pa[4], pb[4];
        const float* Ap = (DUAL_A && 0 >= Ksplit) ? a1 : a0;
#pragma unroll
        for (int r = 0; r < 4; r++) {
            pa[r] = *(const float4*)(Ap + (long long)(bm + row0 + 32 * r) * lda + c4 * 4);
            pb[r] = *(const float4*)(bp + (long long)(bn + row0 + 32 * r) * ldb + c4 * 4);
        }
#pragma unroll
        for (int r = 0; r < 4; r++) {
            uint32_t h0, h1, l0, l1;
            int off = (row0 + 32 * r) * 12 + sts_hi;
            split4(pa[r], h0, h1, l0, l1);
            *(uint2*)(sm + off)     = make_uint2(h0, h1);
            *(uint2*)(sm + off + 4) = make_uint2(l0, l1);
            split4(pb[r], h0, h1, l0, l1);
            *(uint2*)(sm + AREG + off)     = make_uint2(h0, h1);
            *(uint2*)(sm + AREG + off + 4) = make_uint2(l0, l1);
        }
        __syncthreads();
    }

    for (int s = 0; s < nstages; ++s) {
        float4 pa[4], pb[4];
        const bool more = (s + 1 < nstages);
        if (more) {
            const int k0 = (s + 1) << 5;
            const float* Ap; int kl;
            if (DUAL_A && k0 >= Ksplit) { Ap = a1; kl = k0 - Ksplit; }
            else                        { Ap = a0; kl = k0; }
#pragma unroll
            for (int r = 0; r < 4; r++) {
                pa[r] = *(const float4*)(Ap + (long long)(bm + row0 + 32 * r) * lda + kl + c4 * 4);
                pb[r] = *(const float4*)(bp + (long long)(bn + row0 + 32 * r) * ldb + k0 + c4 * 4);
            }
        }

        // ---- compute current stage: 2 k-chunks of 16 ----
        const uint32_t* As = sm + (s & 1) * STAGEF;
        const uint32_t* Bs = As + AREG;
#pragma unroll
        for (int kc = 0; kc < 2; kc++) {
            const uint32_t* Ak0 = As + (2 * kc) * KSS;
            const uint32_t* Ak1 = Ak0 + KSS;
            const uint32_t* Bk0 = Bs + (2 * kc) * KSS;
            const uint32_t* Bk1 = Bk0 + KSS;

            uint32_t ah[4][4], al[4][4], bh[4][2], bl[4][2];
#pragma unroll
            for (int i = 0; i < 4; i++) {
                const int r = warp_m * 64 + i * 16 + g;
                ah[i][0] = Ak0[r * 12 + t];
                ah[i][1] = Ak0[(r + 8) * 12 + t];
                ah[i][2] = Ak1[r * 12 + t];
                ah[i][3] = Ak1[(r + 8) * 12 + t];
                al[i][0] = Ak0[r * 12 + t + 4];
                al[i][1] = Ak0[(r + 8) * 12 + t + 4];
                al[i][2] = Ak1[r * 12 + t + 4];
                al[i][3] = Ak1[(r + 8) * 12 + t + 4];
            }
#pragma unroll
            for (int j = 0; j < 4; j++) {
                const int n = warp_n * 32 + j * 8 + g;
                bh[j][0] = Bk0[n * 12 + t];
                bh[j][1] = Bk1[n * 12 + t];
                bl[j][0] = Bk0[n * 12 + t + 4];
                bl[j][1] = Bk1[n * 12 + t + 4];
            }
#pragma unroll
            for (int i = 0; i < 4; i++)
#pragma unroll
                for (int j = 0; j < 4; j++) {
                    mma16(acc[i][j], ah[i], bh[j]);
                    mma16(acc[i][j], ah[i], bl[j]);
                    mma16(acc[i][j], al[i], bh[j]);
                }
        }

        if (more) {
            uint32_t* nb = sm + ((s + 1) & 1) * STAGEF;
#pragma unroll
            for (int r = 0; r < 4; r++) {
                uint32_t h0, h1, l0, l1;
                int off = (row0 + 32 * r) * 12 + sts_hi;
                split4(pa[r], h0, h1, l0, l1);
                *(uint2*)(nb + off)     = make_uint2(h0, h1);
                *(uint2*)(nb + off + 4) = make_uint2(l0, l1);
                split4(pb[r], h0, h1, l0, l1);
                *(uint2*)(nb + AREG + off)     = make_uint2(h0, h1);
                *(uint2*)(nb + AREG + off + 4) = make_uint2(l0, l1);
            }
        }
        __syncthreads();
    }

    // ---- epilogue: acc -> C (float2 stores, bias/tanh fused) ----
#pragma unroll
    for (int i = 0; i < 4; i++) {
#pragma unroll
        for (int h = 0; h < 2; h++) {
            const int m = bm + warp_m * 64 + i * 16 + g + h * 8;
#pragma unroll
            for (int j = 0; j < 4; j++) {
                const int n = bn + warp_n * 32 + j * 8 + t * 2;
                float x = acc[i][j][h * 2];
                float y = acc[i][j][h * 2 + 1];
                if (BIAS)    { x += __ldg(bias + n); y += __ldg(bias + n + 1); }
                if (TANH_EP) { x = tanhf(x);         y = tanhf(y); }
                *(float2*)(cp + (long long)m * ldc + n) = make_float2(x, y);
            }
        }
    }
}

// ---------------------------------------------------------------------------
// enc (B,S,E) -> encT (B,E,S)
// ---------------------------------------------------------------------------
__global__ __launch_bounds__(256)
void transpose_enc(const float* __restrict__ in, float* __restrict__ out)
{
    __shared__ float tbuf[32][33];
    const int b = blockIdx.z;
    const int s0 = blockIdx.x * 32, e0 = blockIdx.y * 32;
    const float* ip = in + (long long)b * S_ * E_;
    float* op = out + (long long)b * E_ * S_;
    const int x = threadIdx.x;
#pragma unroll
    for (int r = threadIdx.y; r < 32; r += 8)
        tbuf[r][x] = ip[(long long)(s0 + r) * E_ + e0 + x];
    __syncthreads();
#pragma unroll
    for (int r = threadIdx.y; r < 32; r += 8)
        op[(long long)(e0 + r) * S_ + s0 + x] = tbuf[x][r];
}

// ---------------------------------------------------------------------------
// Row softmax over S=1024
// ---------------------------------------------------------------------------
__global__ __launch_bounds__(256)
void softmax_1024(const float* __restrict__ in, float* __restrict__ out)
{
    const long long row = blockIdx.x;
    const float* x = in  + row * 1024;
    float*       y = out + row * 1024;
    const int tid = threadIdx.x, lane = tid & 31, warp = tid >> 5;
    __shared__ float redmax[8], redsum[8];

    float4 v = ((const float4*)x)[tid];
    float mx = fmaxf(fmaxf(v.x, v.y), fmaxf(v.z, v.w));
#pragma unroll
    for (int o = 16; o; o >>= 1) mx = fmaxf(mx, __shfl_xor_sync(~0u, mx, o));
    if (lane == 0) redmax[warp] = mx;
    __syncthreads();
    mx = redmax[0];
#pragma unroll
    for (int w = 1; w < 8; w++) mx = fmaxf(mx, redmax[w]);

    float e0 = __expf(v.x - mx), e1 = __expf(v.y - mx);
    float e2 = __expf(v.z - mx), e3 = __expf(v.w - mx);
    float s = (e0 + e1) + (e2 + e3);
#pragma unroll
    for (int o = 16; o; o >>= 1) s += __shfl_xor_sync(~0u, s, o);
    if (lane == 0) redsum[warp] = s;
    __syncthreads();
    s = redsum[0];
#pragma unroll
    for (int w = 1; w < 8; w++) s += redsum[w];

    const float inv = 1.f / s;
    ((float4*)y)[tid] = make_float4(e0 * inv, e1 * inv, e2 * inv, e3 * inv);
}

// ---------------------------------------------------------------------------
// Launcher
// ---------------------------------------------------------------------------
extern "C" void kernel_launch(void* const* d_in, const int* in_sizes, int n_in,
                              void* d_out, int out_size)
{
    const float* hidden = (const float*)d_in[0];
    const float* enc    = (const float*)d_in[1];
    const float* W_attn = (const float*)d_in[2];
    const float* b_attn = (const float*)d_in[3];
    const float* W_out  = (const float*)d_in[4];

    float* out      = (float*)d_out;
    float* h_tilde  = out;
    float* weights  = out + OUT1;
    float* energies = out + OUT1 + OUT2;

    float *proj, *wc, *encT;
    cudaGetSymbolAddress((void**)&proj, g_proj);
    cudaGetSymbolAddress((void**)&wc,   g_wc);
    cudaGetSymbolAddress((void**)&encT, g_encT);

    cudaFuncSetAttribute(gemm_mma<false, true,  false>,
        cudaFuncAttributeMaxDynamicSharedMemorySize, GEMM_SMEM);
    cudaFuncSetAttribute(gemm_mma<false, false, false>,
        cudaFuncAttributeMaxDynamicSharedMemorySize, GEMM_SMEM);
    cudaFuncSetAttribute(gemm_mma<true,  false, true >,
        cudaFuncAttributeMaxDynamicSharedMemorySize, GEMM_SMEM);

    // enc -> encT (consumed by GEMM 4)
    transpose_enc<<<dim3(S_ / 32, E_ / 32, B_), dim3(32, 8)>>>(enc, encT);

    // 1) proj = enc @ W_attn^T + b : M=16384, N=1024, K=1024
    gemm_mma<false, true, false><<<dim3(D_ / 128, BS_ / 128, 1), 256, GEMM_SMEM>>>(
        enc, nullptr, W_attn, b_attn, proj,
        E_, 0, E_, E_, D_, 0, 0, 0);

    // 2) energies[b] = hidden[b] @ proj[b]^T : batched M=N=K=1024
    gemm_mma<false, false, false><<<dim3(S_ / 128, T_ / 128, B_), 256, GEMM_SMEM>>>(
        hidden, nullptr, proj, nullptr, energies,
        D_, 0, D_, D_, S_,
        (long long)T_ * D_, (long long)S_ * D_, (long long)T_ * S_);

    // 3) softmax
    softmax_1024<<<BT_, 256>>>(energies, weights);

    // 4) wc[b] = weights[b] @ encT[b]^T : batched M=N=K=1024
    gemm_mma<false, false, false><<<dim3(E_ / 128, T_ / 128, B_), 256, GEMM_SMEM>>>(
        weights, nullptr, encT, nullptr, wc,
        S_, 0, S_, S_, E_,
        (long long)T_ * S_, (long long)E_ * S_, (long long)T_ * E_);

    // 5) h_tilde = tanh([wc|hidden] @ W_out^T) : M=16384, N=1024, K=2048
    gemm_mma<true, false, true><<<dim3(D_ / 128, BT_ / 128, 1), 256, GEMM_SMEM>>>(
        wc, hidden, W_out, nullptr, h_tilde,
        E_ + D_, E_, E_, E_ + D_, D_, 0, 0, 0);

    (void)in_sizes; (void)n_in; (void)out_size;
}